// round 12
// baseline (speedup 1.0000x reference)
#include <cuda_runtime.h>
#include <cuda_fp16.h>
#include <cstdint>

// ---------------- Problem constants ----------------
#define NB   16
#define NI   256
#define NO   512
#define WD   512
#define PXY  4225      // 65*65
#define NSTG 72        // 9 taps * 8 chunks of 32 channels

// ---------------- Device scratch ----------------
__device__ float  g_styles[NB * NI];
__device__ float  g_wsq[NO * NI];
__device__ float  g_dcoefs[NB * NO];
__device__ __half g_Bh[NO * 9 * NI];             // [o][tap*256 + i]
__device__ __half g_xth[(size_t)NB * PXY * NI];  // NHWC: [n][y*65+x][i]

__device__ __forceinline__ uint32_t smem_u32(const void* p) {
    return (uint32_t)__cvta_generic_to_shared(p);
}
__device__ __forceinline__ void cp16(uint32_t dst, const void* src) {
    asm volatile("cp.async.cg.shared.global [%0], [%1], 16;\n" :: "r"(dst), "l"(src));
}
__device__ __forceinline__ void ldsm_x4(uint32_t d[4], uint32_t addr) {
    asm volatile("ldmatrix.sync.aligned.m8n8.x4.shared.b16 {%0,%1,%2,%3}, [%4];\n"
                 : "=r"(d[0]), "=r"(d[1]), "=r"(d[2]), "=r"(d[3]) : "r"(addr));
}

// ---------------- K1: fused styles + weight pack ----------------
__global__ void k_sp(const float* __restrict__ w,
                     const float* __restrict__ aw,
                     const float* __restrict__ ab,
                     const float* __restrict__ weight) {
    if (blockIdx.x < 16) {
        __shared__ float sw[WD];
        const int n = blockIdx.x;
        const int i = threadIdx.x;
        for (int d = threadIdx.x; d < WD; d += 256) sw[d] = w[n * WD + d];
        __syncthreads();
        const float* __restrict__ row = aw + (size_t)i * WD;
        float acc = 0.f;
#pragma unroll 8
        for (int d = 0; d < WD; d++) acc += sw[d] * row[d];
        g_styles[n * NI + i] = acc * 0.04419417382415922f + ab[i];
    } else {
        const int gt = (blockIdx.x - 16) * 256 + threadIdx.x;   // 131072
        const int i = gt & (NI - 1);
        const int o = gt >> 8;
        const float* __restrict__ src = weight + ((size_t)o * NI + i) * 9;
        float s = 0.f;
#pragma unroll
        for (int t = 0; t < 9; t++) {
            float v = src[t];
            s += v * v;
            g_Bh[(size_t)o * (9 * NI) + t * NI + i] = __float2half(v);
        }
        g_wsq[o * NI + i] = s;
    }
}

// ---------------- K2: dcoefs ----------------
__global__ void k_dcoefs() {
    __shared__ float s2[NI];
    const int n = blockIdx.x;
    const int o = threadIdx.x;  // 512
    if (o < NI) { float s = g_styles[n * NI + o]; s2[o] = s * s; }
    __syncthreads();
    const float* __restrict__ wr = g_wsq + (size_t)o * NI;
    float acc = 0.f;
#pragma unroll 8
    for (int i = 0; i < NI; i++) acc += s2[i] * wr[i];
    g_dcoefs[n * NO + o] = rsqrtf(acc + 1e-8f);
}

// ---------------- K3: fused FIR + modulate + NHWC transpose (R10 proven) ----------------
#define FW 70
#define SROW (16 * FW)
__global__ __launch_bounds__(256) void k_fir2(const float* __restrict__ x) {
    extern __shared__ float sf[];    // 16*16*70 floats = 71680 B
    const int tid = threadIdx.x;
    const int y0 = blockIdx.x * 13;
    const int i0 = blockIdx.y << 4;
    const int n  = blockIdx.z;
    const float f0 = 0.125f, f1 = 0.375f;

    {
        const int r = tid >> 4, ch = tid & 15;
        float* row = &sf[r * SROW + ch * FW];
        row[0] = 0.f; row[1] = 0.f;
        row[66] = 0.f; row[67] = 0.f; row[68] = 0.f; row[69] = 0.f;
    }
#pragma unroll
    for (int r = 0; r < 16; r++) {
        int g = y0 - 2 + r;
        if (g < 0 || g > 63) {
            for (int idx = tid; idx < 16 * FW; idx += 256)
                sf[r * SROW + idx] = 0.f;
        }
    }
    {
        const float* __restrict__ xb = x + (((size_t)(n << 8) + i0) << 12);
#pragma unroll
        for (int it = 0; it < 16; it++) {
            int idx = it * 256 + tid;
            int q  = idx & 15;
            int ch = (idx >> 4) & 15;
            int r  = idx >> 8;
            int g  = y0 - 2 + r;
            if (g >= 0 && g <= 63) {
                const float4 v = *(const float4*)(xb + ((size_t)ch << 12) + (g << 6) + (q << 2));
                float* d = &sf[r * SROW + ch * FW + 2 + (q << 2)];
                d[0] = v.x; d[1] = v.y; d[2] = v.z; d[3] = v.w;
            }
        }
    }
    __syncthreads();

    const int ch = tid & 15;
    const int q  = tid >> 4;
    const float st = g_styles[(n << 8) + i0 + ch];
    __half* __restrict__ outp = g_xth + ((size_t)n * PXY << 8) + i0 + ch;
#pragma unroll
    for (int j = 0; j < 2; j++) {
        const int xc0 = (j << 5) + (q << 1);
        float h0[16], h1[16];
#pragma unroll
        for (int r = 0; r < 16; r++) {
            const float2* s2 = (const float2*)&sf[r * SROW + ch * FW + xc0];
            const float2 a = s2[0], b = s2[1], c = s2[2];
            h0[r] = f0 * (a.x + b.y) + f1 * (a.y + b.x);
            h1[r] = f0 * (a.y + c.x) + f1 * (b.x + b.y);
        }
#pragma unroll
        for (int y = 0; y < 13; y++) {
            const float v0 = f0 * (h0[y] + h0[y + 3]) + f1 * (h0[y + 1] + h0[y + 2]);
            const float v1 = f0 * (h1[y] + h1[y + 3]) + f1 * (h1[y + 1] + h1[y + 2]);
            const size_t p = (size_t)((y0 + y) * 65 + xc0);
            outp[p << 8] = __float2half(v0 * st);
            outp[(p + 1) << 8] = __float2half(v1 * st);
        }
    }
    if (q == 0) {
        float h[16];
#pragma unroll
        for (int r = 0; r < 16; r++) {
            const float* s = &sf[r * SROW + ch * FW + 64];
            h[r] = f0 * (s[0] + s[3]) + f1 * (s[1] + s[2]);
        }
#pragma unroll
        for (int y = 0; y < 13; y++) {
            const float v = f0 * (h[y] + h[y + 3]) + f1 * (h[y + 1] + h[y + 2]);
            outp[(size_t)((y0 + y) * 65 + 64) << 8] = __float2half(v * st);
        }
    }
}

// ---------------- K4: fp16 implicit-GEMM, 128x128x32 CTA, 4 warps of 64x64 ----------------
// C[16384, 512] = A[16384, 2304] * B[2304, 512]. 128 threads, 3-stage cp.async ring.
// Per warp per kk: 4x ldsm_x4 (A) + 4x ldsm_x4 (B pairs) -> 32 independent mma.
#define ROWB 80u
#define BOFS 10240u
#define BUFB 20480u
__device__ __forceinline__ void mma_f16(float c[4], const uint32_t a[4],
                                        uint32_t b0, uint32_t b1) {
    asm volatile(
        "mma.sync.aligned.m16n8k16.row.col.f32.f16.f16.f32 "
        "{%0,%1,%2,%3}, {%4,%5,%6,%7}, {%8,%9}, {%0,%1,%2,%3};\n"
        : "+f"(c[0]), "+f"(c[1]), "+f"(c[2]), "+f"(c[3])
        : "r"(a[0]), "r"(a[1]), "r"(a[2]), "r"(a[3]), "r"(b0), "r"(b1));
}

__global__ __launch_bounds__(128, 2) void k_gemm(const float* __restrict__ bias,
                                                 float* __restrict__ out) {
    extern __shared__ __align__(16) char dsm[];
    const uint32_t sbase = smem_u32(dsm);

    const int tid  = threadIdx.x;
    const int lane = tid & 31, wid = tid >> 5;
    const int wm = wid & 1, wn = wid >> 1;            // 2 x 2 warp grid, 64x64 each
    const int mblk = blockIdx.y << 7;                 // within one image
    const int obase = blockIdx.x << 7;
    const int n_img = mblk >> 10;
    const int g = lane >> 2, t4 = lane & 3;

    // gmem load mapping: thread t loads full A row t (64B) and full B row t (64B)
    const int m  = mblk + tid;
    const int oh = (m >> 5) & 31, ow = m & 31;
    const __half* __restrict__ xn = g_xth + (size_t)n_img * PXY * NI;
    const __half* __restrict__ bw = g_Bh + (size_t)(obase + tid) * (9 * NI);

    // ldmatrix lane-address bases
    // A: row = wm*64 + mf*16 + (lane&15), col-halfs = kk + ((lane>>4)<<3)
    const uint32_t aOff = (uint32_t)(wm * 64 + (lane & 15)) * ROWB
                        + (uint32_t)((lane >> 4) << 3) * 2u;
    // B x4 pair: rows = wn*64 + nf2*16 + ((lane>>4)<<3) + (lane&7), col = kk + (((lane>>3)&1)<<3)
    const uint32_t bOff = BOFS
                        + (uint32_t)(wn * 64 + ((lane >> 4) << 3) + (lane & 7)) * ROWB
                        + (uint32_t)(((lane >> 3) & 1) << 3) * 2u;
    // cp.async destinations within a buffer
    const uint32_t aDst = (uint32_t)tid * ROWB;
    const uint32_t bDst = BOFS + aDst;

    float acc[4][8][4];
#pragma unroll
    for (int a = 0; a < 4; a++)
#pragma unroll
        for (int b = 0; b < 8; b++)
#pragma unroll
            for (int e = 0; e < 4; e++) acc[a][b][e] = 0.f;

    auto load_stage = [&](int s, uint32_t bufU) {
        const int tp = s >> 3, c = s & 7;
        const int ta = tp / 3, tb = tp - ta * 3;
        const int y  = (oh << 1) + 2 - ta;
        const int xx = (ow << 1) + 2 - tb;
        const __half* asrc = xn + (((size_t)(y * 65 + xx)) << 8) + (c << 5);
#pragma unroll
        for (int v = 0; v < 4; v++)
            cp16(bufU + aDst + v * 16u, asrc + v * 8);
        const __half* bsrc = bw + (tp << 8) + (c << 5);
#pragma unroll
        for (int v = 0; v < 4; v++)
            cp16(bufU + bDst + v * 16u, bsrc + v * 8);
    };

    load_stage(0, sbase);
    asm volatile("cp.async.commit_group;\n" ::: "memory");
    load_stage(1, sbase + BUFB);
    asm volatile("cp.async.commit_group;\n" ::: "memory");

    uint32_t bufIdx = 0;        // s % 3
    for (int s = 0; s < NSTG; s++) {
        asm volatile("cp.async.wait_group 1;\n" ::: "memory");
        __syncthreads();
        if (s + 2 < NSTG) {
            uint32_t nb = bufIdx + 2; if (nb >= 3) nb -= 3;
            load_stage(s + 2, sbase + nb * BUFB);
        }
        asm volatile("cp.async.commit_group;\n" ::: "memory");

        const uint32_t bufU = sbase + bufIdx * BUFB;
        const uint32_t aB = bufU + aOff;
        const uint32_t bB = bufU + bOff;
#pragma unroll
        for (int kk = 0; kk < 32; kk += 16) {
            uint32_t af[4][4], bf[4][4];
#pragma unroll
            for (int mf = 0; mf < 4; mf++)
                ldsm_x4(af[mf], aB + (uint32_t)(mf * 16) * ROWB + (uint32_t)kk * 2u);
#pragma unroll
            for (int nf2 = 0; nf2 < 4; nf2++)
                ldsm_x4(bf[nf2], bB + (uint32_t)(nf2 * 16) * ROWB + (uint32_t)kk * 2u);
#pragma unroll
            for (int mf = 0; mf < 4; mf++)
#pragma unroll
                for (int nf2 = 0; nf2 < 4; nf2++) {
                    mma_f16(acc[mf][2 * nf2],     af[mf], bf[nf2][0], bf[nf2][1]);
                    mma_f16(acc[mf][2 * nf2 + 1], af[mf], bf[nf2][2], bf[nf2][3]);
                }
        }
        if (++bufIdx == 3) bufIdx = 0;
    }

    // Epilogue: y = lrelu(acc * dcoefs[n,o] + bias[o]) * sqrt(2)
    const float SQ2 = 1.4142135623730951f;
#pragma unroll
    for (int mf = 0; mf < 4; mf++) {
#pragma unroll
        for (int half = 0; half < 2; half++) {
            int mm = mblk + (wm << 6) + (mf << 4) + g + (half << 3);
            int sp = mm & 1023;
#pragma unroll
            for (int nf = 0; nf < 8; nf++) {
                int o0 = obase + (wn << 6) + (nf << 3) + (t4 << 1);
#pragma unroll
                for (int e = 0; e < 2; e++) {
                    int o = o0 + e;
                    float v = acc[mf][nf][half * 2 + e];
                    float d = g_dcoefs[(n_img << 9) + o];
                    float val = v * d + bias[o];
                    val = (val >= 0.f ? val : 0.2f * val) * SQ2;
                    out[(((size_t)(n_img << 9) + o) << 10) + sp] = val;
                }
            }
        }
    }
}

// ---------------- Launch ----------------
extern "C" void kernel_launch(void* const* d_in, const int* in_sizes, int n_in,
                              void* d_out, int out_size) {
    const float* x      = (const float*)d_in[0];  // [16,256,64,64]
    const float* w      = (const float*)d_in[1];  // [16,512]
    const float* aw     = (const float*)d_in[2];  // [256,512]
    const float* ab     = (const float*)d_in[3];  // [256]
    const float* weight = (const float*)d_in[4];  // [512,256,3,3]
    const float* bias   = (const float*)d_in[5];  // [512]
    float* out = (float*)d_out;                   // [16,512,32,32]

    cudaFuncSetAttribute(k_fir2, cudaFuncAttributeMaxDynamicSharedMemorySize, 71680);
    cudaFuncSetAttribute(k_gemm, cudaFuncAttributeMaxDynamicSharedMemorySize, 61440);

    k_sp<<<528, 256>>>(w, aw, ab, weight);
    k_dcoefs<<<16, 512>>>();
    k_fir2<<<dim3(5, 16, 16), 256, 71680>>>(x);
    k_gemm<<<dim3(4, 128), 128, 61440>>>(bias, out);
}

// round 13
// speedup vs baseline: 1.1301x; 1.1301x over previous
#include <cuda_runtime.h>
#include <cuda_fp16.h>
#include <cstdint>

// ---------------- Problem constants ----------------
#define NB   16
#define NI   256
#define NO   512
#define WD   512
#define PXY  4225      // 65*65
#define NSTG 72        // 9 taps * 8 chunks of 32 channels

// ---------------- Device scratch ----------------
__device__ float  g_styles[NB * NI];
__device__ float  g_wsq[NO * NI];
__device__ float  g_dcoefs[NB * NO];
__device__ __half g_Bh[NO * 9 * NI];             // [o][tap*256 + i]
__device__ __half g_xth[(size_t)NB * PXY * NI];  // NHWC: [n][y*65+x][i]

__device__ __forceinline__ uint32_t smem_u32(const void* p) {
    return (uint32_t)__cvta_generic_to_shared(p);
}
__device__ __forceinline__ void cp16(uint32_t dst, const void* src) {
    asm volatile("cp.async.cg.shared.global [%0], [%1], 16;\n" :: "r"(dst), "l"(src));
}
__device__ __forceinline__ void ldsm_x4(uint32_t d[4], uint32_t addr) {
    asm volatile("ldmatrix.sync.aligned.m8n8.x4.shared.b16 {%0,%1,%2,%3}, [%4];\n"
                 : "=r"(d[0]), "=r"(d[1]), "=r"(d[2]), "=r"(d[3]) : "r"(addr));
}
__device__ __forceinline__ void ldsm_x2(uint32_t d[2], uint32_t addr) {
    asm volatile("ldmatrix.sync.aligned.m8n8.x2.shared.b16 {%0,%1}, [%2];\n"
                 : "=r"(d[0]), "=r"(d[1]) : "r"(addr));
}

// ---------------- K1: fused styles + weight pack ----------------
__global__ void k_sp(const float* __restrict__ w,
                     const float* __restrict__ aw,
                     const float* __restrict__ ab,
                     const float* __restrict__ weight) {
    if (blockIdx.x < 16) {
        __shared__ float sw[WD];
        const int n = blockIdx.x;
        const int i = threadIdx.x;
        for (int d = threadIdx.x; d < WD; d += 256) sw[d] = w[n * WD + d];
        __syncthreads();
        const float* __restrict__ row = aw + (size_t)i * WD;
        float acc = 0.f;
#pragma unroll 8
        for (int d = 0; d < WD; d++) acc += sw[d] * row[d];
        g_styles[n * NI + i] = acc * 0.04419417382415922f + ab[i];
    } else {
        const int gt = (blockIdx.x - 16) * 256 + threadIdx.x;   // 131072
        const int i = gt & (NI - 1);
        const int o = gt >> 8;
        const float* __restrict__ src = weight + ((size_t)o * NI + i) * 9;
        float s = 0.f;
#pragma unroll
        for (int t = 0; t < 9; t++) {
            float v = src[t];
            s += v * v;
            g_Bh[(size_t)o * (9 * NI) + t * NI + i] = __float2half(v);
        }
        g_wsq[o * NI + i] = s;
    }
}

// ---------------- K2: dcoefs ----------------
__global__ void k_dcoefs() {
    __shared__ float s2[NI];
    const int n = blockIdx.x;
    const int o = threadIdx.x;  // 512
    if (o < NI) { float s = g_styles[n * NI + o]; s2[o] = s * s; }
    __syncthreads();
    const float* __restrict__ wr = g_wsq + (size_t)o * NI;
    float acc = 0.f;
#pragma unroll 8
    for (int i = 0; i < NI; i++) acc += s2[i] * wr[i];
    g_dcoefs[n * NO + o] = rsqrtf(acc + 1e-8f);
}

// ---------------- K3: fused FIR + modulate + NHWC transpose (fp16 smem, LDS.64) ----------------
// smem tile: 16 rows x 16 ch x 68 halfs (cols 0,1 = left pad, 2..65 = x 0..63, 66,67 = right pad).
// Row stride 136B == 2 banks mod 32 -> LDS.64 (4 halfs) conflict-free; all reads 8B-aligned.
// Each thread: channel ch, 4 outputs xc0..xc0+3 per row pair of LDS.64.
#define FWH  68
#define SROWH (16 * FWH)    // 1088 halfs per input row
__global__ __launch_bounds__(256) void k_fir2(const float* __restrict__ x) {
    extern __shared__ __half sh[];       // 16*1088 halfs = 34816 B
    __half2* sh2 = (__half2*)sh;
    const int tid = threadIdx.x;
    const int y0 = blockIdx.x * 13;
    const int i0 = blockIdx.y << 4;
    const int n  = blockIdx.z;
    const float f0 = 0.125f, f1 = 0.375f;
    const __half2 z2 = __floats2half2_rn(0.f, 0.f);

    // zero pad cols {0,1} and {66,67} for each (r, ch): 256 threads exactly
    {
        const int r = tid >> 4, ch = tid & 15;
        const int b2 = (r * SROWH + ch * FWH) >> 1;
        sh2[b2] = z2;          // cols 0,1
        sh2[b2 + 33] = z2;     // cols 66,67
    }
    // zero out-of-range rows entirely (at most 2 per block)
#pragma unroll
    for (int r = 0; r < 16; r++) {
        int g = y0 - 2 + r;
        if (g < 0 || g > 63) {
            for (int idx = tid; idx < SROWH / 2; idx += 256)
                sh2[((r * SROWH) >> 1) + idx] = z2;
        }
    }
    // load valid rows: float4 -> 2x half2
    {
        const float* __restrict__ xb = x + (((size_t)(n << 8) + i0) << 12);
#pragma unroll
        for (int it = 0; it < 16; it++) {
            int idx = it * 256 + tid;
            int q  = idx & 15;
            int ch = (idx >> 4) & 15;
            int r  = idx >> 8;
            int g  = y0 - 2 + r;
            if (g >= 0 && g <= 63) {
                const float4 v = *(const float4*)(xb + ((size_t)ch << 12) + (g << 6) + (q << 2));
                const int d2 = (r * SROWH + ch * FWH + 2 + (q << 2)) >> 1;
                sh2[d2]     = __floats2half2_rn(v.x, v.y);
                sh2[d2 + 1] = __floats2half2_rn(v.z, v.w);
            }
        }
    }
    __syncthreads();

    // vertical pass: thread = (ch, q); outputs xc0..xc0+3, 13 y values
    const int ch = tid & 15;
    const int q  = tid >> 4;              // 0..15
    const int xc0 = q << 2;               // 0..60
    const float st = g_styles[(n << 8) + i0 + ch];
    __half* __restrict__ outp = g_xth + ((size_t)n * PXY << 8) + i0 + ch;

    float h[4][16];
#pragma unroll
    for (int r = 0; r < 16; r++) {
        const __half* rp = sh + r * SROWH + ch * FWH + xc0;   // cols xc0..  (8B aligned)
        const uint2 u0 = *(const uint2*)rp;          // cols xc0..xc0+3
        const uint2 u1 = *(const uint2*)(rp + 4);    // cols xc0+4..xc0+7
        const float2 a0 = __half22float2(*(const __half2*)&u0.x);
        const float2 a1 = __half22float2(*(const __half2*)&u0.y);
        const float2 a2 = __half22float2(*(const __half2*)&u1.x);
        const float2 a3 = __half22float2(*(const __half2*)&u1.y);
        const float c0 = a0.x, c1 = a0.y, c2 = a1.x, c3 = a1.y;
        const float c4 = a2.x, c5 = a2.y, c6 = a3.x;
        h[0][r] = f0 * (c0 + c3) + f1 * (c1 + c2);
        h[1][r] = f0 * (c1 + c4) + f1 * (c2 + c3);
        h[2][r] = f0 * (c2 + c5) + f1 * (c3 + c4);
        h[3][r] = f0 * (c3 + c6) + f1 * (c4 + c5);
    }
#pragma unroll
    for (int y = 0; y < 13; y++) {
        const size_t pbase = (size_t)((y0 + y) * 65 + xc0);
#pragma unroll
        for (int j = 0; j < 4; j++) {
            const float v = f0 * (h[j][y] + h[j][y + 3]) + f1 * (h[j][y + 1] + h[j][y + 2]);
            outp[(pbase + j) << 8] = __float2half(v * st);
        }
    }
    // xc = 64 tail (cols 64..67), handled by q == 0 threads
    if (q == 0) {
        float hh[16];
#pragma unroll
        for (int r = 0; r < 16; r++) {
            const __half* rp = sh + r * SROWH + ch * FWH + 64;
            const uint2 u = *(const uint2*)rp;       // cols 64..67
            const float2 a0 = __half22float2(*(const __half2*)&u.x);
            const float2 a1 = __half22float2(*(const __half2*)&u.y);
            hh[r] = f0 * (a0.x + a1.y) + f1 * (a0.y + a1.x);
        }
#pragma unroll
        for (int y = 0; y < 13; y++) {
            const float v = f0 * (hh[y] + hh[y + 3]) + f1 * (hh[y + 1] + hh[y + 2]);
            outp[(size_t)((y0 + y) * 65 + 64) << 8] = __float2half(v * st);
        }
    }
}

// ---------------- K4: fp16 implicit-GEMM (R10 mainloop, 4-stage ring) ----------------
// C[16384, 512] = A[16384, 2304] * B[2304, 512]; tile 128x128x32, 8 warps (2x4).
#define ROWB 80u
#define BOFS 10240u
#define BUFB 20480u
__device__ __forceinline__ void mma_f16(float c[4], const uint32_t a[4], const uint32_t b[2]) {
    asm volatile(
        "mma.sync.aligned.m16n8k16.row.col.f32.f16.f16.f32 "
        "{%0,%1,%2,%3}, {%4,%5,%6,%7}, {%8,%9}, {%0,%1,%2,%3};\n"
        : "+f"(c[0]), "+f"(c[1]), "+f"(c[2]), "+f"(c[3])
        : "r"(a[0]), "r"(a[1]), "r"(a[2]), "r"(a[3]), "r"(b[0]), "r"(b[1]));
}

__global__ __launch_bounds__(256, 2) void k_gemm(const float* __restrict__ bias,
                                                 float* __restrict__ out) {
    extern __shared__ __align__(16) char dsm[];
    const uint32_t sbase = smem_u32(dsm);

    const int tid  = threadIdx.x;
    const int lane = tid & 31, wid = tid >> 5;
    const int wm = wid & 1, wn = wid >> 1;            // 2 x 4 warp grid
    const int mblk = blockIdx.y << 7;                 // within one image
    const int obase = blockIdx.x << 7;
    const int n_img = mblk >> 10;
    const int g = lane >> 2, t4 = lane & 3;

    const int lr = tid >> 1;
    const int hq = (tid & 1) << 4;
    const int m  = mblk + lr;
    const int oh = (m >> 5) & 31, ow = m & 31;
    const __half* __restrict__ xn = g_xth + (size_t)n_img * PXY * NI;
    const __half* __restrict__ bw = g_Bh + (size_t)(obase + lr) * (9 * NI) + hq;

    const uint32_t aOff = (uint32_t)(wm * 64 + (lane & 15)) * ROWB + (uint32_t)((lane >> 4) << 3) * 2u;
    const uint32_t bOff = BOFS + (uint32_t)(wn * 32 + (lane & 7)) * ROWB
                        + (uint32_t)(((lane >> 3) & 1) << 3) * 2u;
    const uint32_t aDst = (uint32_t)lr * ROWB + (uint32_t)hq * 2u;
    const uint32_t bDst = BOFS + aDst;

    float acc[4][4][4];
#pragma unroll
    for (int a = 0; a < 4; a++)
#pragma unroll
        for (int b = 0; b < 4; b++)
#pragma unroll
            for (int e = 0; e < 4; e++) acc[a][b][e] = 0.f;

    auto load_stage = [&](int s, uint32_t bufU) {
        const int tp = s >> 3, c = s & 7;
        const int ta = tp / 3, tb = tp - ta * 3;
        const int y  = (oh << 1) + 2 - ta;
        const int xx = (ow << 1) + 2 - tb;
        const __half* asrc = xn + (((size_t)(y * 65 + xx)) << 8) + (c << 5) + hq;
        cp16(bufU + aDst, asrc);
        cp16(bufU + aDst + 16, asrc + 8);
        const __half* bsrc = bw + (tp << 8) + (c << 5);
        cp16(bufU + bDst, bsrc);
        cp16(bufU + bDst + 16, bsrc + 8);
    };

    load_stage(0, sbase);
    asm volatile("cp.async.commit_group;\n" ::: "memory");
    load_stage(1, sbase + BUFB);
    asm volatile("cp.async.commit_group;\n" ::: "memory");
    load_stage(2, sbase + 2 * BUFB);
    asm volatile("cp.async.commit_group;\n" ::: "memory");

    for (int s = 0; s < NSTG; s++) {
        asm volatile("cp.async.wait_group 2;\n" ::: "memory");
        __syncthreads();
        if (s + 3 < NSTG)
            load_stage(s + 3, sbase + (uint32_t)((s + 3) & 3) * BUFB);
        asm volatile("cp.async.commit_group;\n" ::: "memory");

        const uint32_t bufU = sbase + (uint32_t)(s & 3) * BUFB;
        const uint32_t aB = bufU + aOff;
        const uint32_t bB = bufU + bOff;
#pragma unroll
        for (int kk = 0; kk < 32; kk += 16) {
            uint32_t af[4][4], bf[4][2];
#pragma unroll
            for (int mf = 0; mf < 4; mf++)
                ldsm_x4(af[mf], aB + (uint32_t)(mf * 16) * ROWB + (uint32_t)kk * 2u);
#pragma unroll
            for (int nf = 0; nf < 4; nf++)
                ldsm_x2(bf[nf], bB + (uint32_t)(nf * 8) * ROWB + (uint32_t)kk * 2u);
#pragma unroll
            for (int mf = 0; mf < 4; mf++)
#pragma unroll
                for (int nf = 0; nf < 4; nf++)
                    mma_f16(acc[mf][nf], af[mf], bf[nf]);
        }
    }

    // Epilogue: y = lrelu(acc * dcoefs[n,o] + bias[o]) * sqrt(2)
    const float SQ2 = 1.4142135623730951f;
#pragma unroll
    for (int mf = 0; mf < 4; mf++) {
#pragma unroll
        for (int half = 0; half < 2; half++) {
            int mm = mblk + (wm << 6) + (mf << 4) + g + (half << 3);
            int sp = mm & 1023;
#pragma unroll
            for (int nf = 0; nf < 4; nf++) {
                int o0 = obase + (wn << 5) + (nf << 3) + (t4 << 1);
#pragma unroll
                for (int e = 0; e < 2; e++) {
                    int o = o0 + e;
                    float v = acc[mf][nf][half * 2 + e];
                    float d = g_dcoefs[(n_img << 9) + o];
                    float val = v * d + bias[o];
                    val = (val >= 0.f ? val : 0.2f * val) * SQ2;
                    out[(((size_t)(n_img << 9) + o) << 10) + sp] = val;
                }
            }
        }
    }
}

// ---------------- Launch ----------------
extern "C" void kernel_launch(void* const* d_in, const int* in_sizes, int n_in,
                              void* d_out, int out_size) {
    const float* x      = (const float*)d_in[0];  // [16,256,64,64]
    const float* w      = (const float*)d_in[1];  // [16,512]
    const float* aw     = (const float*)d_in[2];  // [256,512]
    const float* ab     = (const float*)d_in[3];  // [256]
    const float* weight = (const float*)d_in[4];  // [512,256,3,3]
    const float* bias   = (const float*)d_in[5];  // [512]
    float* out = (float*)d_out;                   // [16,512,32,32]

    cudaFuncSetAttribute(k_fir2, cudaFuncAttributeMaxDynamicSharedMemorySize, 34816);
    cudaFuncSetAttribute(k_gemm, cudaFuncAttributeMaxDynamicSharedMemorySize, 81920);

    k_sp<<<528, 256>>>(w, aw, ab, weight);
    k_dcoefs<<<16, 512>>>();
    k_fir2<<<dim3(5, 16, 16), 256, 34816>>>(x);
    k_gemm<<<dim3(4, 128), 256, 81920>>>(bias, out);
}

// round 14
// speedup vs baseline: 1.3706x; 1.2129x over previous
#include <cuda_runtime.h>
#include <cuda_fp16.h>
#include <cstdint>

// ---------------- Problem constants ----------------
#define NB   16
#define NI   256
#define NO   512
#define WD   512
#define PXY  4225      // 65*65
#define NSTG 72        // 9 taps * 8 chunks of 32 channels

// ---------------- Device scratch ----------------
__device__ float  g_styles[NB * NI];
__device__ float  g_wsq[NO * NI];
__device__ float  g_dcoefs[NB * NO];
__device__ __half g_Bh[NO * 9 * NI];             // [o][tap*256 + i]
__device__ __half g_xth[(size_t)NB * PXY * NI];  // NHWC: [n][y*65+x][i]

__device__ __forceinline__ uint32_t smem_u32(const void* p) {
    return (uint32_t)__cvta_generic_to_shared(p);
}
__device__ __forceinline__ void cp16(uint32_t dst, const void* src) {
    asm volatile("cp.async.cg.shared.global [%0], [%1], 16;\n" :: "r"(dst), "l"(src));
}
__device__ __forceinline__ void ldsm_x4(uint32_t d[4], uint32_t addr) {
    asm volatile("ldmatrix.sync.aligned.m8n8.x4.shared.b16 {%0,%1,%2,%3}, [%4];\n"
                 : "=r"(d[0]), "=r"(d[1]), "=r"(d[2]), "=r"(d[3]) : "r"(addr));
}
__device__ __forceinline__ void ldsm_x2(uint32_t d[2], uint32_t addr) {
    asm volatile("ldmatrix.sync.aligned.m8n8.x2.shared.b16 {%0,%1}, [%2];\n"
                 : "=r"(d[0]), "=r"(d[1]) : "r"(addr));
}

// ---------------- K1: fused styles + weight pack ----------------
__global__ void k_sp(const float* __restrict__ w,
                     const float* __restrict__ aw,
                     const float* __restrict__ ab,
                     const float* __restrict__ weight) {
    if (blockIdx.x < 16) {
        __shared__ float sw[WD];
        const int n = blockIdx.x;
        const int i = threadIdx.x;
        for (int d = threadIdx.x; d < WD; d += 256) sw[d] = w[n * WD + d];
        __syncthreads();
        const float* __restrict__ row = aw + (size_t)i * WD;
        float acc = 0.f;
#pragma unroll 8
        for (int d = 0; d < WD; d++) acc += sw[d] * row[d];
        g_styles[n * NI + i] = acc * 0.04419417382415922f + ab[i];
    } else {
        const int gt = (blockIdx.x - 16) * 256 + threadIdx.x;   // 131072
        const int i = gt & (NI - 1);
        const int o = gt >> 8;
        const float* __restrict__ src = weight + ((size_t)o * NI + i) * 9;
        float s = 0.f;
#pragma unroll
        for (int t = 0; t < 9; t++) {
            float v = src[t];
            s += v * v;
            g_Bh[(size_t)o * (9 * NI) + t * NI + i] = __float2half(v);
        }
        g_wsq[o * NI + i] = s;
    }
}

// ---------------- K2: fused FIR + modulate + NHWC transpose, plus dcoefs column ----------------
// grid (6, 16, 16): blockIdx.x < 5 -> FIR strips; blockIdx.x == 5 -> dcoefs for
// (n = blockIdx.z, o-group = blockIdx.y). Both depend only on k_sp.
#define FWH  68
#define SROWH (16 * FWH)    // 1088 halfs per input row
__global__ __launch_bounds__(256) void k_fir2(const float* __restrict__ x) {
    extern __shared__ __half sh[];       // 16*1088 halfs = 34816 B
    __half2* sh2 = (__half2*)sh;
    const int tid = threadIdx.x;
    const int n  = blockIdx.z;

    if (blockIdx.x == 5) {
        // dcoefs[n, o] = rsqrt(sum_i styles[n,i]^2 * wsq[o,i] + 1e-8), 32 o per block
        const int o = (blockIdx.y << 5) + (tid >> 3);
        const int p = tid & 7;
        const float* __restrict__ wr = g_wsq + (size_t)o * NI + (p << 5);
        const float* __restrict__ st = g_styles + (n << 8) + (p << 5);
        float acc = 0.f;
#pragma unroll
        for (int i = 0; i < 32; i++) { const float s = st[i]; acc += s * s * wr[i]; }
#pragma unroll
        for (int d = 4; d; d >>= 1) acc += __shfl_xor_sync(0xffffffffu, acc, d);
        if (p == 0) g_dcoefs[(n << 9) + o] = rsqrtf(acc + 1e-8f);
        return;
    }

    const int y0 = blockIdx.x * 13;
    const int i0 = blockIdx.y << 4;
    const float f0 = 0.125f, f1 = 0.375f;
    const __half2 z2 = __floats2half2_rn(0.f, 0.f);

    {
        const int r = tid >> 4, ch = tid & 15;
        const int b2 = (r * SROWH + ch * FWH) >> 1;
        sh2[b2] = z2;          // cols 0,1
        sh2[b2 + 33] = z2;     // cols 66,67
    }
#pragma unroll
    for (int r = 0; r < 16; r++) {
        int g = y0 - 2 + r;
        if (g < 0 || g > 63) {
            for (int idx = tid; idx < SROWH / 2; idx += 256)
                sh2[((r * SROWH) >> 1) + idx] = z2;
        }
    }
    {
        const float* __restrict__ xb = x + (((size_t)(n << 8) + i0) << 12);
#pragma unroll
        for (int it = 0; it < 16; it++) {
            int idx = it * 256 + tid;
            int q  = idx & 15;
            int ch = (idx >> 4) & 15;
            int r  = idx >> 8;
            int g  = y0 - 2 + r;
            if (g >= 0 && g <= 63) {
                const float4 v = *(const float4*)(xb + ((size_t)ch << 12) + (g << 6) + (q << 2));
                const int d2 = (r * SROWH + ch * FWH + 2 + (q << 2)) >> 1;
                sh2[d2]     = __floats2half2_rn(v.x, v.y);
                sh2[d2 + 1] = __floats2half2_rn(v.z, v.w);
            }
        }
    }
    __syncthreads();

    const int ch = tid & 15;
    const int q  = tid >> 4;              // 0..15
    const int xc0 = q << 2;               // 0..60
    const float st = g_styles[(n << 8) + i0 + ch];
    __half* __restrict__ outp = g_xth + ((size_t)n * PXY << 8) + i0 + ch;

    float h[4][16];
#pragma unroll
    for (int r = 0; r < 16; r++) {
        const __half* rp = sh + r * SROWH + ch * FWH + xc0;
        const uint2 u0 = *(const uint2*)rp;          // cols xc0..xc0+3
        const uint2 u1 = *(const uint2*)(rp + 4);    // cols xc0+4..xc0+7
        const float2 a0 = __half22float2(*(const __half2*)&u0.x);
        const float2 a1 = __half22float2(*(const __half2*)&u0.y);
        const float2 a2 = __half22float2(*(const __half2*)&u1.x);
        const float2 a3 = __half22float2(*(const __half2*)&u1.y);
        const float c0 = a0.x, c1 = a0.y, c2 = a1.x, c3 = a1.y;
        const float c4 = a2.x, c5 = a2.y, c6 = a3.x;
        h[0][r] = f0 * (c0 + c3) + f1 * (c1 + c2);
        h[1][r] = f0 * (c1 + c4) + f1 * (c2 + c3);
        h[2][r] = f0 * (c2 + c5) + f1 * (c3 + c4);
        h[3][r] = f0 * (c3 + c6) + f1 * (c4 + c5);
    }
#pragma unroll
    for (int y = 0; y < 13; y++) {
        const size_t pbase = (size_t)((y0 + y) * 65 + xc0);
#pragma unroll
        for (int j = 0; j < 4; j++) {
            const float v = f0 * (h[j][y] + h[j][y + 3]) + f1 * (h[j][y + 1] + h[j][y + 2]);
            outp[(pbase + j) << 8] = __float2half(v * st);
        }
    }
    if (q == 0) {
        float hh[16];
#pragma unroll
        for (int r = 0; r < 16; r++) {
            const __half* rp = sh + r * SROWH + ch * FWH + 64;
            const uint2 u = *(const uint2*)rp;       // cols 64..67
            const float2 a0 = __half22float2(*(const __half2*)&u.x);
            const float2 a1 = __half22float2(*(const __half2*)&u.y);
            hh[r] = f0 * (a0.x + a1.y) + f1 * (a0.y + a1.x);
        }
#pragma unroll
        for (int y = 0; y < 13; y++) {
            const float v = f0 * (hh[y] + hh[y + 3]) + f1 * (hh[y + 1] + hh[y + 2]);
            outp[(size_t)((y0 + y) * 65 + 64) << 8] = __float2half(v * st);
        }
    }
}

// ---------------- K3: fp16 implicit-GEMM (R10 mainloop, 4-stage ring, warp kk-stagger) ----------------
#define ROWB 80u
#define BOFS 10240u
#define BUFB 20480u
__device__ __forceinline__ void mma_f16(float c[4], const uint32_t a[4], const uint32_t b[2]) {
    asm volatile(
        "mma.sync.aligned.m16n8k16.row.col.f32.f16.f16.f32 "
        "{%0,%1,%2,%3}, {%4,%5,%6,%7}, {%8,%9}, {%0,%1,%2,%3};\n"
        : "+f"(c[0]), "+f"(c[1]), "+f"(c[2]), "+f"(c[3])
        : "r"(a[0]), "r"(a[1]), "r"(a[2]), "r"(a[3]), "r"(b[0]), "r"(b[1]));
}

__global__ __launch_bounds__(256, 2) void k_gemm(const float* __restrict__ bias,
                                                 float* __restrict__ out) {
    extern __shared__ __align__(16) char dsm[];
    const uint32_t sbase = smem_u32(dsm);

    const int tid  = threadIdx.x;
    const int lane = tid & 31, wid = tid >> 5;
    const int wm = wid & 1, wn = wid >> 1;            // 2 x 4 warp grid
    const int mblk = blockIdx.y << 7;                 // within one image
    const int obase = blockIdx.x << 7;
    const int n_img = mblk >> 10;
    const int g = lane >> 2, t4 = lane & 3;
    const uint32_t kk0 = (uint32_t)(wid & 1) << 4;    // warp-parity kk stagger

    const int lr = tid >> 1;
    const int hq = (tid & 1) << 4;
    const int m  = mblk + lr;
    const int oh = (m >> 5) & 31, ow = m & 31;
    const __half* __restrict__ xn = g_xth + (size_t)n_img * PXY * NI;
    const __half* __restrict__ bw = g_Bh + (size_t)(obase + lr) * (9 * NI) + hq;

    const uint32_t aOff = (uint32_t)(wm * 64 + (lane & 15)) * ROWB + (uint32_t)((lane >> 4) << 3) * 2u;
    const uint32_t bOff = BOFS + (uint32_t)(wn * 32 + (lane & 7)) * ROWB
                        + (uint32_t)(((lane >> 3) & 1) << 3) * 2u;
    const uint32_t aDst = (uint32_t)lr * ROWB + (uint32_t)hq * 2u;
    const uint32_t bDst = BOFS + aDst;

    float acc[4][4][4];
#pragma unroll
    for (int a = 0; a < 4; a++)
#pragma unroll
        for (int b = 0; b < 4; b++)
#pragma unroll
            for (int e = 0; e < 4; e++) acc[a][b][e] = 0.f;

    auto load_stage = [&](int s, uint32_t bufU) {
        const int tp = s >> 3, c = s & 7;
        const int ta = tp / 3, tb = tp - ta * 3;
        const int y  = (oh << 1) + 2 - ta;
        const int xx = (ow << 1) + 2 - tb;
        const __half* asrc = xn + (((size_t)(y * 65 + xx)) << 8) + (c << 5) + hq;
        cp16(bufU + aDst, asrc);
        cp16(bufU + aDst + 16, asrc + 8);
        const __half* bsrc = bw + (tp << 8) + (c << 5);
        cp16(bufU + bDst, bsrc);
        cp16(bufU + bDst + 16, bsrc + 8);
    };

    load_stage(0, sbase);
    asm volatile("cp.async.commit_group;\n" ::: "memory");
    load_stage(1, sbase + BUFB);
    asm volatile("cp.async.commit_group;\n" ::: "memory");
    load_stage(2, sbase + 2 * BUFB);
    asm volatile("cp.async.commit_group;\n" ::: "memory");

    for (int s = 0; s < NSTG; s++) {
        asm volatile("cp.async.wait_group 2;\n" ::: "memory");
        __syncthreads();
        if (s + 3 < NSTG)
            load_stage(s + 3, sbase + (uint32_t)((s + 3) & 3) * BUFB);
        asm volatile("cp.async.commit_group;\n" ::: "memory");

        const uint32_t bufU = sbase + (uint32_t)(s & 3) * BUFB;
        const uint32_t aB = bufU + aOff;
        const uint32_t bB = bufU + bOff;
#pragma unroll
        for (int ph = 0; ph < 2; ph++) {
            const uint32_t kk = kk0 ^ ((uint32_t)ph << 4);
            uint32_t af[4][4], bf[4][2];
#pragma unroll
            for (int mf = 0; mf < 4; mf++)
                ldsm_x4(af[mf], aB + (uint32_t)(mf * 16) * ROWB + kk * 2u);
#pragma unroll
            for (int nf = 0; nf < 4; nf++)
                ldsm_x2(bf[nf], bB + (uint32_t)(nf * 8) * ROWB + kk * 2u);
#pragma unroll
            for (int mf = 0; mf < 4; mf++)
#pragma unroll
                for (int nf = 0; nf < 4; nf++)
                    mma_f16(acc[mf][nf], af[mf], bf[nf]);
        }
    }

    // Epilogue: y = lrelu(acc * dcoefs[n,o] + bias[o]) * sqrt(2)
    const float SQ2 = 1.4142135623730951f;
    float dpre[4][2], bpre[4][2];
#pragma unroll
    for (int nf = 0; nf < 4; nf++) {
        const int o0 = obase + (wn << 5) + (nf << 3) + (t4 << 1);
#pragma unroll
        for (int e = 0; e < 2; e++) {
            dpre[nf][e] = g_dcoefs[(n_img << 9) + o0 + e];
            bpre[nf][e] = bias[o0 + e];
        }
    }
#pragma unroll
    for (int mf = 0; mf < 4; mf++) {
#pragma unroll
        for (int half = 0; half < 2; half++) {
            int mm = mblk + (wm << 6) + (mf << 4) + g + (half << 3);
            int sp = mm & 1023;
#pragma unroll
            for (int nf = 0; nf < 4; nf++) {
                int o0 = obase + (wn << 5) + (nf << 3) + (t4 << 1);
#pragma unroll
                for (int e = 0; e < 2; e++) {
                    float val = acc[mf][nf][half * 2 + e] * dpre[nf][e] + bpre[nf][e];
                    val = (val >= 0.f ? val : 0.2f * val) * SQ2;
                    out[(((size_t)(n_img << 9) + o0 + e) << 10) + sp] = val;
                }
            }
        }
    }
}

// ---------------- Launch ----------------
extern "C" void kernel_launch(void* const* d_in, const int* in_sizes, int n_in,
                              void* d_out, int out_size) {
    const float* x      = (const float*)d_in[0];  // [16,256,64,64]
    const float* w      = (const float*)d_in[1];  // [16,512]
    const float* aw     = (const float*)d_in[2];  // [256,512]
    const float* ab     = (const float*)d_in[3];  // [256]
    const float* weight = (const float*)d_in[4];  // [512,256,3,3]
    const float* bias   = (const float*)d_in[5];  // [512]
    float* out = (float*)d_out;                   // [16,512,32,32]

    cudaFuncSetAttribute(k_fir2, cudaFuncAttributeMaxDynamicSharedMemorySize, 34816);
    cudaFuncSetAttribute(k_gemm, cudaFuncAttributeMaxDynamicSharedMemorySize, 81920);

    k_sp<<<528, 256>>>(w, aw, ab, weight);
    k_fir2<<<dim3(6, 16, 16), 256, 34816>>>(x);
    k_gemm<<<dim3(4, 128), 256, 81920>>>(bias, out);
}

// round 15
// speedup vs baseline: 1.7687x; 1.2904x over previous
#include <cuda_runtime.h>
#include <cuda_fp16.h>
#include <cstdint>

// ---------------- Problem constants ----------------
#define NB   16
#define NI   256
#define NO   512
#define WD   512
#define PXY  4225      // 65*65
#define NSTG 72        // 9 taps * 8 chunks of 32 channels

// ---------------- Device scratch ----------------
__device__ float  g_styles[NB * NI];
__device__ float  g_wsq[NO * NI];
__device__ float  g_dcoefs[NB * NO];
__device__ __half g_Bh[NO * 9 * NI];             // [o][tap*256 + i]
__device__ __half g_xth[(size_t)NB * PXY * NI];  // NHWC: [n][y*65+x][i]

__device__ __forceinline__ uint32_t smem_u32(const void* p) {
    return (uint32_t)__cvta_generic_to_shared(p);
}
__device__ __forceinline__ void cp16(uint32_t dst, const void* src) {
    asm volatile("cp.async.cg.shared.global [%0], [%1], 16;\n" :: "r"(dst), "l"(src));
}
__device__ __forceinline__ void ldsm_x4(uint32_t d[4], uint32_t addr) {
    asm volatile("ldmatrix.sync.aligned.m8n8.x4.shared.b16 {%0,%1,%2,%3}, [%4];\n"
                 : "=r"(d[0]), "=r"(d[1]), "=r"(d[2]), "=r"(d[3]) : "r"(addr));
}
__device__ __forceinline__ void ldsm_x2(uint32_t d[2], uint32_t addr) {
    asm volatile("ldmatrix.sync.aligned.m8n8.x2.shared.b16 {%0,%1}, [%2];\n"
                 : "=r"(d[0]), "=r"(d[1]) : "r"(addr));
}

// ---------------- K1: fused styles (coalesced, warp-per-i) + weight pack ----------------
// blocks 0..255: styles — block (n = b>>4, i0 = (b&15)*16); warp w computes i0+2w, i0+2w+1.
// blocks 256..767: pack g_Bh + g_wsq (one thread per (o,i)).
__global__ void k_sp(const float* __restrict__ w,
                     const float* __restrict__ aw,
                     const float* __restrict__ ab,
                     const float* __restrict__ weight) {
    const int b = blockIdx.x;
    const int tid = threadIdx.x;
    if (b < 256) {
        const int n  = b >> 4;
        const int i0 = (b & 15) << 4;
        const int wd = tid >> 5, lane = tid & 31;
        const float* __restrict__ wv = w + n * WD;
#pragma unroll
        for (int ii = 0; ii < 2; ii++) {
            const int i = i0 + (wd << 1) + ii;
            const float* __restrict__ row = aw + (size_t)i * WD;
            float acc = 0.f;
#pragma unroll
            for (int k = 0; k < 16; k++) {
                const int d = lane + (k << 5);
                acc += wv[d] * row[d];
            }
#pragma unroll
            for (int dlt = 16; dlt; dlt >>= 1)
                acc += __shfl_xor_sync(0xffffffffu, acc, dlt);
            if (lane == 0)
                g_styles[(n << 8) + i] = acc * 0.04419417382415922f + ab[i];
        }
    } else {
        const int gt = (b - 256) * 256 + tid;            // 131072
        const int i = gt & (NI - 1);
        const int o = gt >> 8;
        const float* __restrict__ src = weight + ((size_t)o * NI + i) * 9;
        float s = 0.f;
#pragma unroll
        for (int t = 0; t < 9; t++) {
            float v = src[t];
            s += v * v;
            g_Bh[(size_t)o * (9 * NI) + t * NI + i] = __float2half(v);
        }
        g_wsq[o * NI + i] = s;
    }
}

// ---------------- K2: fused FIR + modulate + NHWC transpose, plus dcoefs column ----------------
#define FWH  68
#define SROWH (16 * FWH)    // 1088 halfs per input row
__global__ __launch_bounds__(256) void k_fir2(const float* __restrict__ x) {
    extern __shared__ __half sh[];       // 16*1088 halfs = 34816 B
    __half2* sh2 = (__half2*)sh;
    const int tid = threadIdx.x;
    const int n  = blockIdx.z;

    if (blockIdx.x == 5) {
        const int o = (blockIdx.y << 5) + (tid >> 3);
        const int p = tid & 7;
        const float* __restrict__ wr = g_wsq + (size_t)o * NI + (p << 5);
        const float* __restrict__ st = g_styles + (n << 8) + (p << 5);
        float acc = 0.f;
#pragma unroll
        for (int i = 0; i < 32; i++) { const float s = st[i]; acc += s * s * wr[i]; }
#pragma unroll
        for (int d = 4; d; d >>= 1) acc += __shfl_xor_sync(0xffffffffu, acc, d);
        if (p == 0) g_dcoefs[(n << 9) + o] = rsqrtf(acc + 1e-8f);
        return;
    }

    const int y0 = blockIdx.x * 13;
    const int i0 = blockIdx.y << 4;
    const float f0 = 0.125f, f1 = 0.375f;
    const __half2 z2 = __floats2half2_rn(0.f, 0.f);

    {
        const int r = tid >> 4, ch = tid & 15;
        const int b2 = (r * SROWH + ch * FWH) >> 1;
        sh2[b2] = z2;          // cols 0,1
        sh2[b2 + 33] = z2;     // cols 66,67
    }
#pragma unroll
    for (int r = 0; r < 16; r++) {
        int g = y0 - 2 + r;
        if (g < 0 || g > 63) {
            for (int idx = tid; idx < SROWH / 2; idx += 256)
                sh2[((r * SROWH) >> 1) + idx] = z2;
        }
    }
    {
        const float* __restrict__ xb = x + (((size_t)(n << 8) + i0) << 12);
#pragma unroll
        for (int it = 0; it < 16; it++) {
            int idx = it * 256 + tid;
            int q  = idx & 15;
            int ch = (idx >> 4) & 15;
            int r  = idx >> 8;
            int g  = y0 - 2 + r;
            if (g >= 0 && g <= 63) {
                const float4 v = *(const float4*)(xb + ((size_t)ch << 12) + (g << 6) + (q << 2));
                const int d2 = (r * SROWH + ch * FWH + 2 + (q << 2)) >> 1;
                sh2[d2]     = __floats2half2_rn(v.x, v.y);
                sh2[d2 + 1] = __floats2half2_rn(v.z, v.w);
            }
        }
    }
    __syncthreads();

    const int ch = tid & 15;
    const int q  = tid >> 4;              // 0..15
    const int xc0 = q << 2;               // 0..60
    const float st = g_styles[(n << 8) + i0 + ch];
    __half* __restrict__ outp = g_xth + ((size_t)n * PXY << 8) + i0 + ch;

    float h[4][16];
#pragma unroll
    for (int r = 0; r < 16; r++) {
        const __half* rp = sh + r * SROWH + ch * FWH + xc0;
        const uint2 u0 = *(const uint2*)rp;          // cols xc0..xc0+3
        const uint2 u1 = *(const uint2*)(rp + 4);    // cols xc0+4..xc0+7
        const float2 a0 = __half22float2(*(const __half2*)&u0.x);
        const float2 a1 = __half22float2(*(const __half2*)&u0.y);
        const float2 a2 = __half22float2(*(const __half2*)&u1.x);
        const float2 a3 = __half22float2(*(const __half2*)&u1.y);
        const float c0 = a0.x, c1 = a0.y, c2 = a1.x, c3 = a1.y;
        const float c4 = a2.x, c5 = a2.y, c6 = a3.x;
        h[0][r] = f0 * (c0 + c3) + f1 * (c1 + c2);
        h[1][r] = f0 * (c1 + c4) + f1 * (c2 + c3);
        h[2][r] = f0 * (c2 + c5) + f1 * (c3 + c4);
        h[3][r] = f0 * (c3 + c6) + f1 * (c4 + c5);
    }
#pragma unroll
    for (int y = 0; y < 13; y++) {
        const size_t pbase = (size_t)((y0 + y) * 65 + xc0);
#pragma unroll
        for (int j = 0; j < 4; j++) {
            const float v = f0 * (h[j][y] + h[j][y + 3]) + f1 * (h[j][y + 1] + h[j][y + 2]);
            outp[(pbase + j) << 8] = __float2half(v * st);
        }
    }
    if (q == 0) {
        float hh[16];
#pragma unroll
        for (int r = 0; r < 16; r++) {
            const __half* rp = sh + r * SROWH + ch * FWH + 64;
            const uint2 u = *(const uint2*)rp;       // cols 64..67
            const float2 a0 = __half22float2(*(const __half2*)&u.x);
            const float2 a1 = __half22float2(*(const __half2*)&u.y);
            hh[r] = f0 * (a0.x + a1.y) + f1 * (a0.y + a1.x);
        }
#pragma unroll
        for (int y = 0; y < 13; y++) {
            const float v = f0 * (hh[y] + hh[y + 3]) + f1 * (hh[y + 1] + hh[y + 2]);
            outp[(size_t)((y0 + y) * 65 + 64) << 8] = __float2half(v * st);
        }
    }
}

// ---------------- K3: fp16 implicit-GEMM (R14 proven: 4-stage ring + warp kk-stagger) ----------------
#define ROWB 80u
#define BOFS 10240u
#define BUFB 20480u
__device__ __forceinline__ void mma_f16(float c[4], const uint32_t a[4], const uint32_t b[2]) {
    asm volatile(
        "mma.sync.aligned.m16n8k16.row.col.f32.f16.f16.f32 "
        "{%0,%1,%2,%3}, {%4,%5,%6,%7}, {%8,%9}, {%0,%1,%2,%3};\n"
        : "+f"(c[0]), "+f"(c[1]), "+f"(c[2]), "+f"(c[3])
        : "r"(a[0]), "r"(a[1]), "r"(a[2]), "r"(a[3]), "r"(b[0]), "r"(b[1]));
}

__global__ __launch_bounds__(256, 2) void k_gemm(const float* __restrict__ bias,
                                                 float* __restrict__ out) {
    extern __shared__ __align__(16) char dsm[];
    const uint32_t sbase = smem_u32(dsm);

    const int tid  = threadIdx.x;
    const int lane = tid & 31, wid = tid >> 5;
    const int wm = wid & 1, wn = wid >> 1;            // 2 x 4 warp grid
    const int mblk = blockIdx.y << 7;                 // within one image
    const int obase = blockIdx.x << 7;
    const int n_img = mblk >> 10;
    const int g = lane >> 2, t4 = lane & 3;
    const uint32_t kk0 = (uint32_t)(wid & 1) << 4;    // warp-parity kk stagger

    const int lr = tid >> 1;
    const int hq = (tid & 1) << 4;
    const int m  = mblk + lr;
    const int oh = (m >> 5) & 31, ow = m & 31;
    const __half* __restrict__ xn = g_xth + (size_t)n_img * PXY * NI;
    const __half* __restrict__ bw = g_Bh + (size_t)(obase + lr) * (9 * NI) + hq;

    const uint32_t aOff = (uint32_t)(wm * 64 + (lane & 15)) * ROWB + (uint32_t)((lane >> 4) << 3) * 2u;
    const uint32_t bOff = BOFS + (uint32_t)(wn * 32 + (lane & 7)) * ROWB
                        + (uint32_t)(((lane >> 3) & 1) << 3) * 2u;
    const uint32_t aDst = (uint32_t)lr * ROWB + (uint32_t)hq * 2u;
    const uint32_t bDst = BOFS + aDst;

    float acc[4][4][4];
#pragma unroll
    for (int a = 0; a < 4; a++)
#pragma unroll
        for (int b = 0; b < 4; b++)
#pragma unroll
            for (int e = 0; e < 4; e++) acc[a][b][e] = 0.f;

    auto load_stage = [&](int s, uint32_t bufU) {
        const int tp = s >> 3, c = s & 7;
        const int ta = tp / 3, tb = tp - ta * 3;
        const int y  = (oh << 1) + 2 - ta;
        const int xx = (ow << 1) + 2 - tb;
        const __half* asrc = xn + (((size_t)(y * 65 + xx)) << 8) + (c << 5) + hq;
        cp16(bufU + aDst, asrc);
        cp16(bufU + aDst + 16, asrc + 8);
        const __half* bsrc = bw + (tp << 8) + (c << 5);
        cp16(bufU + bDst, bsrc);
        cp16(bufU + bDst + 16, bsrc + 8);
    };

    load_stage(0, sbase);
    asm volatile("cp.async.commit_group;\n" ::: "memory");
    load_stage(1, sbase + BUFB);
    asm volatile("cp.async.commit_group;\n" ::: "memory");
    load_stage(2, sbase + 2 * BUFB);
    asm volatile("cp.async.commit_group;\n" ::: "memory");

    for (int s = 0; s < NSTG; s++) {
        asm volatile("cp.async.wait_group 2;\n" ::: "memory");
        __syncthreads();
        if (s + 3 < NSTG)
            load_stage(s + 3, sbase + (uint32_t)((s + 3) & 3) * BUFB);
        asm volatile("cp.async.commit_group;\n" ::: "memory");

        const uint32_t bufU = sbase + (uint32_t)(s & 3) * BUFB;
        const uint32_t aB = bufU + aOff;
        const uint32_t bB = bufU + bOff;
#pragma unroll
        for (int ph = 0; ph < 2; ph++) {
            const uint32_t kk = kk0 ^ ((uint32_t)ph << 4);
            uint32_t af[4][4], bf[4][2];
#pragma unroll
            for (int mf = 0; mf < 4; mf++)
                ldsm_x4(af[mf], aB + (uint32_t)(mf * 16) * ROWB + kk * 2u);
#pragma unroll
            for (int nf = 0; nf < 4; nf++)
                ldsm_x2(bf[nf], bB + (uint32_t)(nf * 8) * ROWB + kk * 2u);
#pragma unroll
            for (int mf = 0; mf < 4; mf++)
#pragma unroll
                for (int nf = 0; nf < 4; nf++)
                    mma_f16(acc[mf][nf], af[mf], bf[nf]);
        }
    }

    // Epilogue: y = lrelu(acc * dcoefs[n,o] + bias[o]) * sqrt(2)
    const float SQ2 = 1.4142135623730951f;
    float dpre[4][2], bpre[4][2];
#pragma unroll
    for (int nf = 0; nf < 4; nf++) {
        const int o0 = obase + (wn << 5) + (nf << 3) + (t4 << 1);
#pragma unroll
        for (int e = 0; e < 2; e++) {
            dpre[nf][e] = g_dcoefs[(n_img << 9) + o0 + e];
            bpre[nf][e] = bias[o0 + e];
        }
    }
#pragma unroll
    for (int mf = 0; mf < 4; mf++) {
#pragma unroll
        for (int half = 0; half < 2; half++) {
            int mm = mblk + (wm << 6) + (mf << 4) + g + (half << 3);
            int sp = mm & 1023;
#pragma unroll
            for (int nf = 0; nf < 4; nf++) {
                int o0 = obase + (wn << 5) + (nf << 3) + (t4 << 1);
#pragma unroll
                for (int e = 0; e < 2; e++) {
                    float val = acc[mf][nf][half * 2 + e] * dpre[nf][e] + bpre[nf][e];
                    val = (val >= 0.f ? val : 0.2f * val) * SQ2;
                    out[(((size_t)(n_img << 9) + o0 + e) << 10) + sp] = val;
                }
            }
        }
    }
}

// ---------------- Launch ----------------
extern "C" void kernel_launch(void* const* d_in, const int* in_sizes, int n_in,
                              void* d_out, int out_size) {
    const float* x      = (const float*)d_in[0];  // [16,256,64,64]
    const float* w      = (const float*)d_in[1];  // [16,512]
    const float* aw     = (const float*)d_in[2];  // [256,512]
    const float* ab     = (const float*)d_in[3];  // [256]
    const float* weight = (const float*)d_in[4];  // [512,256,3,3]
    const float* bias   = (const float*)d_in[5];  // [512]
    float* out = (float*)d_out;                   // [16,512,32,32]

    cudaFuncSetAttribute(k_fir2, cudaFuncAttributeMaxDynamicSharedMemorySize, 34816);
    cudaFuncSetAttribute(k_gemm, cudaFuncAttributeMaxDynamicSharedMemorySize, 81920);

    k_sp<<<768, 256>>>(w, aw, ab, weight);
    k_fir2<<<dim3(6, 16, 16), 256, 34816>>>(x);
    k_gemm<<<dim3(4, 128), 256, 81920>>>(bias, out);
}